// round 8
// baseline (speedup 1.0000x reference)
#include <cuda_runtime.h>
#include <stdint.h>
#include <math.h>

#define NF 64
#define NFC 32              /* filters per chunk */
#define NC 51
#define LG 1001
#define NB 16
#define NH 256
#define NW 256
#define GP 262              /* NH + 2*3 padded adjoint grid */

// ---------------- scratch ----------------
__device__ float  d_wn [NF * 49];
__device__ float  d_wnf[NF * 49];
__device__ float2 d_tab2[NF * 1000];
__device__ float  d_lut[3];
__device__ float  d_phi[(size_t)NB * NF * NH * NW];
__device__ float  d_g  [2 * NB * GP * GP];

// ---------------- f32x2 helpers ----------------
__device__ __forceinline__ unsigned long long pack2(float lo, float hi) {
    unsigned long long r;
    asm("mov.b64 %0, {%1, %2};" : "=l"(r) : "f"(lo), "f"(hi));
    return r;
}
__device__ __forceinline__ void fma2(unsigned long long& d,
                                     unsigned long long a, unsigned long long b) {
    asm("fma.rn.f32x2 %0, %1, %2, %3;" : "=l"(d) : "l"(a), "l"(b), "l"(d));
}

// ---------------- cp.async helpers ----------------
__device__ __forceinline__ void cp_async16_z(void* sdst, const void* gsrc, int src_bytes) {
    unsigned int sa = (unsigned int)__cvta_generic_to_shared(sdst);
    asm volatile("cp.async.cg.shared.global [%0], [%1], 16, %2;\n"
                 :: "r"(sa), "l"(gsrc), "r"(src_bytes));
}
__device__ __forceinline__ void cp_commit() { asm volatile("cp.async.commit_group;\n"); }
__device__ __forceinline__ void cp_wait0()  { asm volatile("cp.async.wait_group 0;\n"); }

// ---------------- prep 1 ----------------
__global__ void prep_weights(const float* __restrict__ cw,
                             const float* __restrict__ sf,
                             const float* __restrict__ grid)
{
    int f = threadIdx.x;
    if (f < NF) {
        float s = 0.f;
        for (int k = 0; k < 49; ++k) s += cw[f * 49 + k];
        float mean = s / 49.0f;
        float ss = 0.f;
        for (int k = 0; k < 49; ++k) {
            float v = cw[f * 49 + k] - mean;
            ss += v * v;
        }
        float sc = sf[f] / sqrtf(ss);
        for (int k = 0; k < 49; ++k) {
            float v = (cw[f * 49 + k] - mean) * sc;
            d_wn[f * 49 + k] = v;
            int p = k / 7, q = k % 7;
            d_wnf[f * 49 + (6 - p) * 7 + (6 - q)] = v;
        }
    }
    if (threadIdx.x == 0) {
        d_lut[0] = grid[0];
        d_lut[1] = grid[LG - 1];
        d_lut[2] = 1.0f / (grid[1] - grid[0]);
    }
}

// ---------------- prep 2 ----------------
__global__ void prep_table(const float* __restrict__ rw,
                           const float* __restrict__ centers,
                           const float* __restrict__ grid)
{
    __shared__ float tl[LG];
    __shared__ float cs[NC];
    __shared__ float rs[NC];
    int f = blockIdx.x;
    int t = threadIdx.x;
    if (t < NC) { cs[t] = centers[t]; rs[t] = rw[f * NC + t]; }
    __syncthreads();
    for (int l = t; l < LG; l += blockDim.x) {
        float g = grid[l];
        float s = 0.f;
        #pragma unroll 1
        for (int c = 0; c < NC; ++c) {
            float dd = 0.25f * (g - cs[c]);
            s += rs[c] * expf(-0.5f * dd * dd);
        }
        tl[l] = s;
    }
    __syncthreads();
    for (int l = t; l < LG - 1; l += blockDim.x)
        d_tab2[f * 1000 + l] = make_float2(tl[l], tl[l + 1]);
}

// vertical stencil, packed: one input smem row feeds 8 output rows x (2 cols packed)
__device__ __forceinline__ void stencil_row2(const float* __restrict__ src, int t0,
                                             const unsigned long long* __restrict__ w2,
                                             unsigned long long acc[8])
{
    float seg[8];
    *reinterpret_cast<float2*>(&seg[0]) = *reinterpret_cast<const float2*>(src);
    *reinterpret_cast<float2*>(&seg[2]) = *reinterpret_cast<const float2*>(src + 2);
    *reinterpret_cast<float2*>(&seg[4]) = *reinterpret_cast<const float2*>(src + 4);
    *reinterpret_cast<float2*>(&seg[6]) = *reinterpret_cast<const float2*>(src + 6);
    unsigned long long pr[7];
    #pragma unroll
    for (int q = 0; q < 7; ++q) pr[q] = pack2(seg[q], seg[q + 1]);
    #pragma unroll
    for (int i = 0; i < 8; ++i) {
        int p = t0 - i;
        if (p >= 0 && p < 7) {
            #pragma unroll
            for (int q = 0; q < 7; ++q)
                fma2(acc[i], w2[p * 7 + q], pr[q]);
        }
    }
}

// ---------------- kernel B: forward conv + LUT -> phi ----------------
// 128 threads, tile 32x64, micro-tile 8 rows x 2 cols, f32x2 packed FMA
__global__ void __launch_bounds__(128, 2) fwd_kernel(const float* __restrict__ x)
{
    __shared__ float  xs[38][72];
    __shared__ float2 ws2[NFC * 49];   // duplicated weights (w, w)

    int b  = blockIdx.z;
    int i0 = blockIdx.y * 32;
    int jt = blockIdx.x & 3;
    int fc = blockIdx.x >> 2;
    int j0 = jt * 64;
    int f0 = fc * NFC;
    int tid = threadIdx.x;

    const float* xb = x + (size_t)b * NH * NW;

    for (int tpos = tid; tpos < 38 * 70; tpos += 128) {
        int r = tpos / 70, c = tpos - r * 70;
        int gi = i0 - 3 + r;
        int gj = j0 - 3 + c;
        gi = (gi < 0) ? (-1 - gi) : ((gi >= NH) ? (2 * NH - 1 - gi) : gi);
        gj = (gj < 0) ? (-1 - gj) : ((gj >= NW) ? (2 * NW - 1 - gj) : gj);
        xs[r][c] = xb[gi * NW + gj];
    }
    for (int tpos = tid; tpos < NFC * 49; tpos += 128) {
        float v = d_wn[f0 * 49 + tpos];
        ws2[tpos] = make_float2(v, v);
    }
    __syncthreads();

    float g0 = d_lut[0], gmax = d_lut[1], invstep = d_lut[2];

    int lane = tid & 31, wrp = tid >> 5;
    int li = wrp * 8;
    int lj = lane * 2;

    for (int ff = 0; ff < NFC; ++ff) {
        int f = f0 + ff;
        unsigned long long w2[49];
        #pragma unroll
        for (int k = 0; k < 49; ++k)
            w2[k] = *reinterpret_cast<const unsigned long long*>(&ws2[ff * 49 + k]);

        unsigned long long acc[8];
        #pragma unroll
        for (int i = 0; i < 8; ++i) acc[i] = 0ull;

        #pragma unroll
        for (int t0 = 0; t0 < 14; ++t0)
            stencil_row2(&xs[li + t0][lj], t0, w2, acc);

        const float2* tf = d_tab2 + f * 1000;
        float* op = d_phi + ((((size_t)b * NF + f) * NH + (i0 + li)) * NW + (j0 + lj));
        #pragma unroll
        for (int i = 0; i < 8; ++i) {
            float2 a = *reinterpret_cast<float2*>(&acc[i]);
            float v0 = fminf(fmaxf(a.x, g0), gmax);
            float v1 = fminf(fmaxf(a.y, g0), gmax);
            float pos0 = (v0 - g0) * invstep;
            float pos1 = (v1 - g0) * invstep;
            int idx0 = (int)floorf(pos0); idx0 = idx0 < 0 ? 0 : (idx0 > 999 ? 999 : idx0);
            int idx1 = (int)floorf(pos1); idx1 = idx1 < 0 ? 0 : (idx1 > 999 ? 999 : idx1);
            float fr0 = pos0 - (float)idx0;
            float fr1 = pos1 - (float)idx1;
            float2 tv0 = __ldg(tf + idx0);
            float2 tv1 = __ldg(tf + idx1);
            float2 o;
            o.x = tv0.x * (1.0f - fr0) + tv0.y * fr0;
            o.y = tv1.x * (1.0f - fr1) + tv1.y * fr1;
            *reinterpret_cast<float2*>(op + (size_t)i * NW) = o;
        }
    }
}

// ---------------- kernel C: adjoint conv -> per-chunk g ----------------
// 128 threads, tile 32x64 on padded grid, micro-tile 8x2, f32x2, cp.async dbl buffer
__global__ void __launch_bounds__(128, 2) bwd_kernel()
{
    __shared__ float  ps[2][38][84];   // col c <-> gj = n0 - 8 + c
    __shared__ float2 ws2[NFC * 49];

    int b  = blockIdx.z;
    int m0 = blockIdx.y * 32;
    int nt = blockIdx.x % 5;
    int fc = blockIdx.x / 5;
    int n0 = nt * 64;
    int f0 = fc * NFC;
    int tid = threadIdx.x;

    for (int tpos = tid; tpos < NFC * 49; tpos += 128) {
        float v = d_wnf[f0 * 49 + tpos];
        ws2[tpos] = make_float2(v, v);
    }

    int lane = tid & 31, wrp = tid >> 5;
    int li = wrp * 8;
    int lj = lane * 2;

    unsigned long long acc[8];
    #pragma unroll
    for (int i = 0; i < 8; ++i) acc[i] = 0ull;

    const float* phib = d_phi + ((size_t)b * NF + f0) * NH * NW;

    #define BWD_FILL(BUF, PF)                                                   \
        for (int tpos = tid; tpos < 38 * 20; tpos += 128) {                     \
            int r = tpos / 20, c4 = tpos - r * 20;                              \
            int gi = m0 - 6 + r;                                                \
            int gj = n0 - 8 + c4 * 4;                                           \
            bool inb = (gi >= 0) & (gi < NH) & (gj >= 0) & (gj < NW);           \
            const float* src = inb ? ((PF) + gi * NW + gj) : (PF);              \
            cp_async16_z(&ps[BUF][r][c4 * 4], src, inb ? 16 : 0);               \
        }

    BWD_FILL(0, phib)
    cp_commit();

    int buf = 0;
    for (int ff = 0; ff < NFC; ++ff) {
        cp_wait0();
        __syncthreads();

        if (ff + 1 < NFC) {
            const float* pf = phib + (size_t)(ff + 1) * NH * NW;
            int ob = buf ^ 1;
            BWD_FILL(ob, pf)
            cp_commit();
        }

        unsigned long long w2[49];
        #pragma unroll
        for (int k = 0; k < 49; ++k)
            w2[k] = *reinterpret_cast<const unsigned long long*>(&ws2[ff * 49 + k]);

        #pragma unroll
        for (int t0 = 0; t0 < 14; ++t0)
            stencil_row2(&ps[buf][li + t0][lj + 2], t0, w2, acc);
        buf ^= 1;
    }
    #undef BWD_FILL

    float* gout = d_g + (size_t)fc * NB * GP * GP + (size_t)b * GP * GP;
    #pragma unroll
    for (int i = 0; i < 8; ++i) {
        int m = m0 + li + i;
        int n = n0 + lj;
        float2 a = *reinterpret_cast<float2*>(&acc[i]);
        if (m < GP) {
            if (n + 1 < GP) {
                *reinterpret_cast<float2*>(gout + m * GP + n) = a;
            } else if (n < GP) {
                gout[m * GP + n] = a.x;
            }
        }
    }
}

// ---------------- kernel D: fold + residual + prox ----------------
__global__ void finish_kernel(const float* __restrict__ input,
                              const float* __restrict__ noisy,
                              const float* __restrict__ a_cond,
                              float* __restrict__ out)
{
    int t = blockIdx.x * blockDim.x + threadIdx.x;
    if (t >= NB * NH * NW) return;
    int b   = t >> 16;
    int rem = t & 65535;
    int i = rem >> 8, j = rem & 255;

    const float* gb0 = d_g + (size_t)b * GP * GP;
    const float* gb1 = gb0 + (size_t)NB * GP * GP;

    int mi[2], nj[2];
    int nm = 1, nn = 1;
    mi[0] = i + 3;
    nj[0] = j + 3;
    if (i < 3)       mi[nm++] = 2 - i;
    if (i >= NH - 3) mi[nm++] = 2 * NH + 2 - i;
    if (j < 3)       nj[nn++] = 2 - j;
    if (j >= NW - 3) nj[nn++] = 2 * NW + 2 - j;

    float r = 0.f;
    for (int a = 0; a < nm; ++a)
        for (int c = 0; c < nn; ++c) {
            int off = mi[a] * GP + nj[c];
            r += gb0[off] + gb1[off];
        }

    float av = a_cond[b];
    float z = input[t] - r;
    float d = z - av;
    out[t] = 0.5f * (d + sqrtf(d * d + 4.0f * av * noisy[t]));
}

// ---------------- launch ----------------
extern "C" void kernel_launch(void* const* d_in, const int* in_sizes, int n_in,
                              void* d_out, int out_size)
{
    const float* input   = (const float*)d_in[0];
    const float* noisy   = (const float*)d_in[1];
    const float* a_cond  = (const float*)d_in[2];
    const float* cw      = (const float*)d_in[3];
    const float* sf      = (const float*)d_in[4];
    const float* rw      = (const float*)d_in[5];
    const float* centers = (const float*)d_in[6];
    const float* grid    = (const float*)d_in[7];
    float* out = (float*)d_out;

    prep_weights<<<1, 64>>>(cw, sf, grid);
    prep_table<<<NF, 128>>>(rw, centers, grid);
    fwd_kernel<<<dim3(8, 8, NB), 128>>>(input);
    bwd_kernel<<<dim3(10, 9, NB), 128>>>();
    finish_kernel<<<(NB * NH * NW + 255) / 256, 256>>>(input, noisy, a_cond, out);
}

// round 9
// speedup vs baseline: 1.2451x; 1.2451x over previous
#include <cuda_runtime.h>
#include <stdint.h>
#include <math.h>

#define NF 64
#define NFC 32              /* filters per chunk */
#define NC 51
#define LG 1001
#define NB 16
#define NH 256
#define NW 256
#define GP 262              /* NH + 2*3 padded adjoint grid */

// ---------------- scratch ----------------
__device__ float  d_wn [NF * 49];
__device__ float  d_wnf[NF * 49];
__device__ float2 d_tab2[NF * 1000];
__device__ float  d_lut[3];
__device__ float  d_phi[(size_t)NB * NF * NH * NW];
__device__ float  d_g  [2 * NB * GP * GP];

// ---------------- cp.async helpers ----------------
__device__ __forceinline__ void cp_async16_z(void* sdst, const void* gsrc, int src_bytes) {
    unsigned int sa = (unsigned int)__cvta_generic_to_shared(sdst);
    asm volatile("cp.async.cg.shared.global [%0], [%1], 16, %2;\n"
                 :: "r"(sa), "l"(gsrc), "r"(src_bytes));
}
__device__ __forceinline__ void cp_commit() { asm volatile("cp.async.commit_group;\n"); }
__device__ __forceinline__ void cp_wait0()  { asm volatile("cp.async.wait_group 0;\n"); }

// ---------------- prep 1 ----------------
__global__ void prep_weights(const float* __restrict__ cw,
                             const float* __restrict__ sf,
                             const float* __restrict__ grid)
{
    int f = threadIdx.x;
    if (f < NF) {
        float s = 0.f;
        for (int k = 0; k < 49; ++k) s += cw[f * 49 + k];
        float mean = s / 49.0f;
        float ss = 0.f;
        for (int k = 0; k < 49; ++k) {
            float v = cw[f * 49 + k] - mean;
            ss += v * v;
        }
        float sc = sf[f] / sqrtf(ss);
        for (int k = 0; k < 49; ++k) {
            float v = (cw[f * 49 + k] - mean) * sc;
            d_wn[f * 49 + k] = v;
            int p = k / 7, q = k % 7;
            d_wnf[f * 49 + (6 - p) * 7 + (6 - q)] = v;
        }
    }
    if (threadIdx.x == 0) {
        d_lut[0] = grid[0];
        d_lut[1] = grid[LG - 1];
        d_lut[2] = 1.0f / (grid[1] - grid[0]);
    }
}

// ---------------- prep 2 ----------------
__global__ void prep_table(const float* __restrict__ rw,
                           const float* __restrict__ centers,
                           const float* __restrict__ grid)
{
    __shared__ float tl[LG];
    __shared__ float cs[NC];
    __shared__ float rs[NC];
    int f = blockIdx.x;
    int t = threadIdx.x;
    if (t < NC) { cs[t] = centers[t]; rs[t] = rw[f * NC + t]; }
    __syncthreads();
    for (int l = t; l < LG; l += blockDim.x) {
        float g = grid[l];
        float s = 0.f;
        #pragma unroll 1
        for (int c = 0; c < NC; ++c) {
            float dd = 0.25f * (g - cs[c]);
            s += rs[c] * expf(-0.5f * dd * dd);
        }
        tl[l] = s;
    }
    __syncthreads();
    for (int l = t; l < LG - 1; l += blockDim.x)
        d_tab2[f * 1000 + l] = make_float2(tl[l], tl[l + 1]);
}

// -------- two-pass vertical stencil: live weight window <= 28 registers --------
// pass A: kernel rows p in [0,4)  -> weights wA[28], input rows t0 = 0..10
// pass B: kernel rows p in [4,7)  -> weights wB[21], input rows t0 = 4..13
__device__ __forceinline__ void load_seg(float seg[8], const float* __restrict__ src)
{
    *reinterpret_cast<float2*>(&seg[0]) = *reinterpret_cast<const float2*>(src);
    *reinterpret_cast<float2*>(&seg[2]) = *reinterpret_cast<const float2*>(src + 2);
    *reinterpret_cast<float2*>(&seg[4]) = *reinterpret_cast<const float2*>(src + 4);
    *reinterpret_cast<float2*>(&seg[6]) = *reinterpret_cast<const float2*>(src + 6);
}

__device__ __forceinline__ void stencil_rowA(const float* __restrict__ src, int t0,
                                             const float* __restrict__ wA,
                                             float acc[8][2])
{
    float seg[8];
    load_seg(seg, src);
    #pragma unroll
    for (int i = 0; i < 8; ++i) {
        int p = t0 - i;
        if (p >= 0 && p < 4) {
            #pragma unroll
            for (int q = 0; q < 7; ++q) {
                acc[i][0] = fmaf(wA[p * 7 + q], seg[q],     acc[i][0]);
                acc[i][1] = fmaf(wA[p * 7 + q], seg[q + 1], acc[i][1]);
            }
        }
    }
}

__device__ __forceinline__ void stencil_rowB(const float* __restrict__ src, int t0,
                                             const float* __restrict__ wB,
                                             float acc[8][2])
{
    float seg[8];
    load_seg(seg, src);
    #pragma unroll
    for (int i = 0; i < 8; ++i) {
        int p = t0 - i;
        if (p >= 4 && p < 7) {
            #pragma unroll
            for (int q = 0; q < 7; ++q) {
                acc[i][0] = fmaf(wB[(p - 4) * 7 + q], seg[q],     acc[i][0]);
                acc[i][1] = fmaf(wB[(p - 4) * 7 + q], seg[q + 1], acc[i][1]);
            }
        }
    }
}

// ---------------- kernel B: forward conv + LUT -> phi ----------------
// 128 threads, tile 32x64, micro-tile 8 rows x 2 cols (warp = contiguous row segment)
__global__ void __launch_bounds__(128) fwd_kernel(const float* __restrict__ x)
{
    __shared__ float xs[38][72];
    __shared__ float ws[NFC * 49];

    int b  = blockIdx.z;
    int i0 = blockIdx.y * 32;
    int jt = blockIdx.x & 3;
    int fc = blockIdx.x >> 2;
    int j0 = jt * 64;
    int f0 = fc * NFC;
    int tid = threadIdx.x;

    const float* xb = x + (size_t)b * NH * NW;

    for (int tpos = tid; tpos < 38 * 70; tpos += 128) {
        int r = tpos / 70, c = tpos - r * 70;
        int gi = i0 - 3 + r;
        int gj = j0 - 3 + c;
        gi = (gi < 0) ? (-1 - gi) : ((gi >= NH) ? (2 * NH - 1 - gi) : gi);
        gj = (gj < 0) ? (-1 - gj) : ((gj >= NW) ? (2 * NW - 1 - gj) : gj);
        xs[r][c] = xb[gi * NW + gj];
    }
    for (int tpos = tid; tpos < NFC * 49; tpos += 128) ws[tpos] = d_wn[f0 * 49 + tpos];
    __syncthreads();

    float g0 = d_lut[0], gmax = d_lut[1], invstep = d_lut[2];

    int lane = tid & 31, wrp = tid >> 5;
    int li = wrp * 8;       // output row base in tile
    int lj = lane * 2;      // output col base in tile

    for (int ff = 0; ff < NFC; ++ff) {
        int f = f0 + ff;

        float acc[8][2];
        #pragma unroll
        for (int i = 0; i < 8; ++i) { acc[i][0] = 0.f; acc[i][1] = 0.f; }

        {
            float wA[28];
            #pragma unroll
            for (int k = 0; k < 28; ++k) wA[k] = ws[ff * 49 + k];
            #pragma unroll
            for (int t0 = 0; t0 < 11; ++t0)
                stencil_rowA(&xs[li + t0][lj], t0, wA, acc);
        }
        {
            float wB[21];
            #pragma unroll
            for (int k = 0; k < 21; ++k) wB[k] = ws[ff * 49 + 28 + k];
            #pragma unroll
            for (int t0 = 4; t0 < 14; ++t0)
                stencil_rowB(&xs[li + t0][lj], t0, wB, acc);
        }

        const float2* tf = d_tab2 + f * 1000;
        float* op = d_phi + ((((size_t)b * NF + f) * NH + (i0 + li)) * NW + (j0 + lj));
        #pragma unroll
        for (int i = 0; i < 8; ++i) {
            float2 o;
            float v0 = fminf(fmaxf(acc[i][0], g0), gmax);
            float v1 = fminf(fmaxf(acc[i][1], g0), gmax);
            float pos0 = (v0 - g0) * invstep;
            float pos1 = (v1 - g0) * invstep;
            int idx0 = (int)floorf(pos0); idx0 = idx0 < 0 ? 0 : (idx0 > 999 ? 999 : idx0);
            int idx1 = (int)floorf(pos1); idx1 = idx1 < 0 ? 0 : (idx1 > 999 ? 999 : idx1);
            float fr0 = pos0 - (float)idx0;
            float fr1 = pos1 - (float)idx1;
            float2 tv0 = __ldg(tf + idx0);
            float2 tv1 = __ldg(tf + idx1);
            o.x = tv0.x * (1.0f - fr0) + tv0.y * fr0;
            o.y = tv1.x * (1.0f - fr1) + tv1.y * fr1;
            *reinterpret_cast<float2*>(op + (size_t)i * NW) = o;
        }
    }
}

// ---------------- kernel C: adjoint conv -> per-chunk g ----------------
// 128 threads, tile 32x64 on padded grid, micro-tile 8x2, cp.async double buffer
__global__ void __launch_bounds__(128) bwd_kernel()
{
    __shared__ float ps[2][38][84];   // col c <-> gj = n0 - 8 + c
    __shared__ float ws[NFC * 49];

    int b  = blockIdx.z;
    int m0 = blockIdx.y * 32;
    int nt = blockIdx.x % 5;
    int fc = blockIdx.x / 5;
    int n0 = nt * 64;
    int f0 = fc * NFC;
    int tid = threadIdx.x;

    for (int tpos = tid; tpos < NFC * 49; tpos += 128) ws[tpos] = d_wnf[f0 * 49 + tpos];

    int lane = tid & 31, wrp = tid >> 5;
    int li = wrp * 8;
    int lj = lane * 2;

    float acc[8][2];
    #pragma unroll
    for (int i = 0; i < 8; ++i) { acc[i][0] = 0.f; acc[i][1] = 0.f; }

    const float* phib = d_phi + ((size_t)b * NF + f0) * NH * NW;

    #define BWD_FILL(BUF, PF)                                                   \
        for (int tpos = tid; tpos < 38 * 20; tpos += 128) {                     \
            int r = tpos / 20, c4 = tpos - r * 20;                              \
            int gi = m0 - 6 + r;                                                \
            int gj = n0 - 8 + c4 * 4;                                           \
            bool inb = (gi >= 0) & (gi < NH) & (gj >= 0) & (gj < NW);           \
            const float* src = inb ? ((PF) + gi * NW + gj) : (PF);              \
            cp_async16_z(&ps[BUF][r][c4 * 4], src, inb ? 16 : 0);               \
        }

    BWD_FILL(0, phib)
    cp_commit();

    int buf = 0;
    for (int ff = 0; ff < NFC; ++ff) {
        cp_wait0();
        __syncthreads();

        if (ff + 1 < NFC) {
            const float* pf = phib + (size_t)(ff + 1) * NH * NW;
            int ob = buf ^ 1;
            BWD_FILL(ob, pf)
            cp_commit();
        }

        {
            float wA[28];
            #pragma unroll
            for (int k = 0; k < 28; ++k) wA[k] = ws[ff * 49 + k];
            #pragma unroll
            for (int t0 = 0; t0 < 11; ++t0)
                stencil_rowA(&ps[buf][li + t0][lj + 2], t0, wA, acc);
        }
        {
            float wB[21];
            #pragma unroll
            for (int k = 0; k < 21; ++k) wB[k] = ws[ff * 49 + 28 + k];
            #pragma unroll
            for (int t0 = 4; t0 < 14; ++t0)
                stencil_rowB(&ps[buf][li + t0][lj + 2], t0, wB, acc);
        }
        buf ^= 1;
    }
    #undef BWD_FILL

    float* gout = d_g + (size_t)fc * NB * GP * GP + (size_t)b * GP * GP;
    #pragma unroll
    for (int i = 0; i < 8; ++i) {
        int m = m0 + li + i;
        int n = n0 + lj;
        if (m < GP) {
            if (n + 1 < GP) {
                *reinterpret_cast<float2*>(gout + m * GP + n) =
                    make_float2(acc[i][0], acc[i][1]);
            } else if (n < GP) {
                gout[m * GP + n] = acc[i][0];
            }
        }
    }
}

// ---------------- kernel D: fold + residual + prox ----------------
__global__ void finish_kernel(const float* __restrict__ input,
                              const float* __restrict__ noisy,
                              const float* __restrict__ a_cond,
                              float* __restrict__ out)
{
    int t = blockIdx.x * blockDim.x + threadIdx.x;
    if (t >= NB * NH * NW) return;
    int b   = t >> 16;
    int rem = t & 65535;
    int i = rem >> 8, j = rem & 255;

    const float* gb0 = d_g + (size_t)b * GP * GP;
    const float* gb1 = gb0 + (size_t)NB * GP * GP;

    int mi[2], nj[2];
    int nm = 1, nn = 1;
    mi[0] = i + 3;
    nj[0] = j + 3;
    if (i < 3)       mi[nm++] = 2 - i;
    if (i >= NH - 3) mi[nm++] = 2 * NH + 2 - i;
    if (j < 3)       nj[nn++] = 2 - j;
    if (j >= NW - 3) nj[nn++] = 2 * NW + 2 - j;

    float r = 0.f;
    for (int a = 0; a < nm; ++a)
        for (int c = 0; c < nn; ++c) {
            int off = mi[a] * GP + nj[c];
            r += gb0[off] + gb1[off];
        }

    float av = a_cond[b];
    float z = input[t] - r;
    float d = z - av;
    out[t] = 0.5f * (d + sqrtf(d * d + 4.0f * av * noisy[t]));
}

// ---------------- launch ----------------
extern "C" void kernel_launch(void* const* d_in, const int* in_sizes, int n_in,
                              void* d_out, int out_size)
{
    const float* input   = (const float*)d_in[0];
    const float* noisy   = (const float*)d_in[1];
    const float* a_cond  = (const float*)d_in[2];
    const float* cw      = (const float*)d_in[3];
    const float* sf      = (const float*)d_in[4];
    const float* rw      = (const float*)d_in[5];
    const float* centers = (const float*)d_in[6];
    const float* grid    = (const float*)d_in[7];
    float* out = (float*)d_out;

    prep_weights<<<1, 64>>>(cw, sf, grid);
    prep_table<<<NF, 128>>>(rw, centers, grid);
    fwd_kernel<<<dim3(8, 8, NB), 128>>>(input);
    bwd_kernel<<<dim3(10, 9, NB), 128>>>();
    finish_kernel<<<(NB * NH * NW + 255) / 256, 256>>>(input, noisy, a_cond, out);
}

// round 10
// speedup vs baseline: 1.2815x; 1.0292x over previous
#include <cuda_runtime.h>
#include <stdint.h>
#include <math.h>

#define NF 64
#define NFC 32              /* filters per chunk */
#define NC 51
#define LG 1001
#define NB 16
#define NH 256
#define NW 256
#define GP 262              /* NH + 2*3 padded adjoint grid */

// ---------------- scratch ----------------
__device__ float  d_wn [NF * 49];
__device__ float  d_wnf[NF * 49];
__device__ float2 d_tab2[NF * 1000];
__device__ float  d_lut[3];
__device__ float  d_phi[(size_t)NB * NF * NH * NW];
__device__ float  d_g  [2 * NB * GP * GP];

// ---------------- cp.async helpers ----------------
__device__ __forceinline__ void cp_async16_z(void* sdst, const void* gsrc, int src_bytes) {
    unsigned int sa = (unsigned int)__cvta_generic_to_shared(sdst);
    asm volatile("cp.async.cg.shared.global [%0], [%1], 16, %2;\n"
                 :: "r"(sa), "l"(gsrc), "r"(src_bytes));
}
__device__ __forceinline__ void cp_commit() { asm volatile("cp.async.commit_group;\n"); }
__device__ __forceinline__ void cp_wait0()  { asm volatile("cp.async.wait_group 0;\n"); }

__device__ __forceinline__ unsigned cvt_tf32(float v) {
    unsigned u;
    asm("cvt.rna.tf32.f32 %0, %1;" : "=r"(u) : "f"(v));
    return u;
}

__device__ __forceinline__ void mma_tf32(float& c0, float& c1, float& c2, float& c3,
                                         unsigned a0, unsigned a1, unsigned a2, unsigned a3,
                                         unsigned b0, unsigned b1) {
    asm volatile(
        "mma.sync.aligned.m16n8k8.row.col.f32.tf32.tf32.f32 "
        "{%0,%1,%2,%3}, {%4,%5,%6,%7}, {%8,%9}, {%0,%1,%2,%3};"
        : "+f"(c0), "+f"(c1), "+f"(c2), "+f"(c3)
        : "r"(a0), "r"(a1), "r"(a2), "r"(a3), "r"(b0), "r"(b1));
}

// ---------------- prep 1 ----------------
__global__ void prep_weights(const float* __restrict__ cw,
                             const float* __restrict__ sf,
                             const float* __restrict__ grid)
{
    int f = threadIdx.x;
    if (f < NF) {
        float s = 0.f;
        for (int k = 0; k < 49; ++k) s += cw[f * 49 + k];
        float mean = s / 49.0f;
        float ss = 0.f;
        for (int k = 0; k < 49; ++k) {
            float v = cw[f * 49 + k] - mean;
            ss += v * v;
        }
        float sc = sf[f] / sqrtf(ss);
        for (int k = 0; k < 49; ++k) {
            float v = (cw[f * 49 + k] - mean) * sc;
            d_wn[f * 49 + k] = v;
            int p = k / 7, q = k % 7;
            d_wnf[f * 49 + (6 - p) * 7 + (6 - q)] = v;
        }
    }
    if (threadIdx.x == 0) {
        d_lut[0] = grid[0];
        d_lut[1] = grid[LG - 1];
        d_lut[2] = 1.0f / (grid[1] - grid[0]);
    }
}

// ---------------- prep 2 ----------------
__global__ void prep_table(const float* __restrict__ rw,
                           const float* __restrict__ centers,
                           const float* __restrict__ grid)
{
    __shared__ float tl[LG];
    __shared__ float cs[NC];
    __shared__ float rs[NC];
    int f = blockIdx.x;
    int t = threadIdx.x;
    if (t < NC) { cs[t] = centers[t]; rs[t] = rw[f * NC + t]; }
    __syncthreads();
    for (int l = t; l < LG; l += blockDim.x) {
        float g = grid[l];
        float s = 0.f;
        #pragma unroll 1
        for (int c = 0; c < NC; ++c) {
            float dd = 0.25f * (g - cs[c]);
            s += rs[c] * expf(-0.5f * dd * dd);
        }
        tl[l] = s;
    }
    __syncthreads();
    for (int l = t; l < LG - 1; l += blockDim.x)
        d_tab2[f * 1000 + l] = make_float2(tl[l], tl[l + 1]);
}

// ---------------- kernel B: forward conv via mma.sync tf32 + LUT -> phi ----------------
// Block: 128 threads (4 warps). Pixel tile 8 rows x 64 cols, 32 filters per block.
// Warp w: output rows {2w, 2w+1}; 4 m-chunks of 16 pixels along x per row.
// GEMM: u[px, f] = sum_k xs_patch[px, k] * W[k, f], K = 49 -> 56 zero-padded.
__global__ void __launch_bounds__(128) fwd_kernel(const float* __restrict__ x)
{
    __shared__ float    xs[14][72];        // 8 out rows + 6 halo, 70 cols used
    __shared__ unsigned ws[56 * 32];       // tf32 weights, [k][f], rows 49..55 zero

    int b  = blockIdx.z;
    int i0 = blockIdx.y * 8;
    int xt = blockIdx.x & 3;
    int fc = blockIdx.x >> 2;
    int x0 = xt * 64;
    int f0 = fc * NFC;
    int tid = threadIdx.x;

    const float* xb_ptr = x + (size_t)b * NH * NW;

    // x tile + halo, symmetric padding
    for (int tpos = tid; tpos < 14 * 70; tpos += 128) {
        int r = tpos / 70, c = tpos - r * 70;
        int gi = i0 - 3 + r;
        int gj = x0 - 3 + c;
        gi = (gi < 0) ? (-1 - gi) : ((gi >= NH) ? (2 * NH - 1 - gi) : gi);
        gj = (gj < 0) ? (-1 - gj) : ((gj >= NW) ? (2 * NW - 1 - gj) : gj);
        xs[r][c] = xb_ptr[gi * NW + gj];
    }
    // weights: ws[k*32 + n] = tf32(wn[f0+n][k]), zero for k >= 49
    for (int tpos = tid; tpos < 56 * 32; tpos += 128) {
        int k = tpos >> 5, n = tpos & 31;
        ws[tpos] = (k < 49) ? cvt_tf32(d_wn[(f0 + n) * 49 + k]) : 0u;
    }
    __syncthreads();

    float g0 = d_lut[0], gmax = d_lut[1], invstep = d_lut[2];

    int lane = tid & 31, wrp = tid >> 5;
    int lam = lane & 3;         // threadID-in-group
    int grp = lane >> 2;        // groupID

    // per-thread A offsets: for kk, half h: c = kk*8 + lam + 4h, clamped to 48
    int offA[7][2];
    #pragma unroll
    for (int kk = 0; kk < 7; ++kk) {
        #pragma unroll
        for (int h = 0; h < 2; ++h) {
            int c = kk * 8 + lam + 4 * h;
            if (c > 48) c = 48;        // B row is zero there; read anything valid
            offA[kk][h] = (c / 7) * 72 + (c % 7);
        }
    }

    // B fragments: bfr[n][kk][0/1], held for whole block
    unsigned bfr[4][7][2];
    #pragma unroll
    for (int n = 0; n < 4; ++n)
        #pragma unroll
        for (int kk = 0; kk < 7; ++kk) {
            bfr[n][kk][0] = ws[(kk * 8 + lam) * 32 + n * 8 + grp];
            bfr[n][kk][1] = ws[(kk * 8 + lam + 4) * 32 + n * 8 + grp];
        }

    const float* xsf = &xs[0][0];

    // 8 m-tiles per warp: 2 rows x 4 chunks of 16 pixels
    #pragma unroll 1
    for (int mt = 0; mt < 8; ++mt) {
        int py = wrp * 2 + (mt >> 2);
        int xb = (mt & 3) * 16;
        int base = py * 72 + xb + grp;

        float acc[4][4];
        #pragma unroll
        for (int n = 0; n < 4; ++n)
            #pragma unroll
            for (int j = 0; j < 4; ++j) acc[n][j] = 0.f;

        #pragma unroll
        for (int kk = 0; kk < 7; ++kk) {
            unsigned a0 = __float_as_uint(xsf[base +     offA[kk][0]]);
            unsigned a1 = __float_as_uint(xsf[base + 8 + offA[kk][0]]);
            unsigned a2 = __float_as_uint(xsf[base +     offA[kk][1]]);
            unsigned a3 = __float_as_uint(xsf[base + 8 + offA[kk][1]]);
            #pragma unroll
            for (int n = 0; n < 4; ++n)
                mma_tf32(acc[n][0], acc[n][1], acc[n][2], acc[n][3],
                         a0, a1, a2, a3, bfr[n][kk][0], bfr[n][kk][1]);
        }

        // epilogue: LUT + store. acc[n][j]: pixel = x0+xb+grp+8*(j>>1), filter = f0+n*8+2*lam+(j&1)
        int y = i0 + py;
        #pragma unroll
        for (int n = 0; n < 4; ++n) {
            #pragma unroll
            for (int j = 0; j < 4; ++j) {
                int f  = f0 + n * 8 + 2 * lam + (j & 1);
                int px = x0 + xb + grp + ((j >> 1) << 3);
                float v = fminf(fmaxf(acc[n][j], g0), gmax);
                float pos = (v - g0) * invstep;
                int idx = (int)floorf(pos);
                idx = idx < 0 ? 0 : (idx > 999 ? 999 : idx);
                float fr = pos - (float)idx;
                float2 tv = __ldg(d_tab2 + f * 1000 + idx);
                d_phi[(((size_t)(b * NF + f)) << 16) + (y << 8) + px] =
                    tv.x * (1.0f - fr) + tv.y * fr;
            }
        }
    }
}

// -------- two-pass vertical stencil (scalar bwd, unchanged from R9) --------
__device__ __forceinline__ void load_seg(float seg[8], const float* __restrict__ src)
{
    *reinterpret_cast<float2*>(&seg[0]) = *reinterpret_cast<const float2*>(src);
    *reinterpret_cast<float2*>(&seg[2]) = *reinterpret_cast<const float2*>(src + 2);
    *reinterpret_cast<float2*>(&seg[4]) = *reinterpret_cast<const float2*>(src + 4);
    *reinterpret_cast<float2*>(&seg[6]) = *reinterpret_cast<const float2*>(src + 6);
}

__device__ __forceinline__ void stencil_rowA(const float* __restrict__ src, int t0,
                                             const float* __restrict__ wA,
                                             float acc[8][2])
{
    float seg[8];
    load_seg(seg, src);
    #pragma unroll
    for (int i = 0; i < 8; ++i) {
        int p = t0 - i;
        if (p >= 0 && p < 4) {
            #pragma unroll
            for (int q = 0; q < 7; ++q) {
                acc[i][0] = fmaf(wA[p * 7 + q], seg[q],     acc[i][0]);
                acc[i][1] = fmaf(wA[p * 7 + q], seg[q + 1], acc[i][1]);
            }
        }
    }
}

__device__ __forceinline__ void stencil_rowB(const float* __restrict__ src, int t0,
                                             const float* __restrict__ wB,
                                             float acc[8][2])
{
    float seg[8];
    load_seg(seg, src);
    #pragma unroll
    for (int i = 0; i < 8; ++i) {
        int p = t0 - i;
        if (p >= 4 && p < 7) {
            #pragma unroll
            for (int q = 0; q < 7; ++q) {
                acc[i][0] = fmaf(wB[(p - 4) * 7 + q], seg[q],     acc[i][0]);
                acc[i][1] = fmaf(wB[(p - 4) * 7 + q], seg[q + 1], acc[i][1]);
            }
        }
    }
}

// ---------------- kernel C: adjoint conv -> per-chunk g (unchanged R9) ----------------
__global__ void __launch_bounds__(128) bwd_kernel()
{
    __shared__ float ps[2][38][84];
    __shared__ float ws[NFC * 49];

    int b  = blockIdx.z;
    int m0 = blockIdx.y * 32;
    int nt = blockIdx.x % 5;
    int fc = blockIdx.x / 5;
    int n0 = nt * 64;
    int f0 = fc * NFC;
    int tid = threadIdx.x;

    for (int tpos = tid; tpos < NFC * 49; tpos += 128) ws[tpos] = d_wnf[f0 * 49 + tpos];

    int lane = tid & 31, wrp = tid >> 5;
    int li = wrp * 8;
    int lj = lane * 2;

    float acc[8][2];
    #pragma unroll
    for (int i = 0; i < 8; ++i) { acc[i][0] = 0.f; acc[i][1] = 0.f; }

    const float* phib = d_phi + ((size_t)b * NF + f0) * NH * NW;

    #define BWD_FILL(BUF, PF)                                                   \
        for (int tpos = tid; tpos < 38 * 20; tpos += 128) {                     \
            int r = tpos / 20, c4 = tpos - r * 20;                              \
            int gi = m0 - 6 + r;                                                \
            int gj = n0 - 8 + c4 * 4;                                           \
            bool inb = (gi >= 0) & (gi < NH) & (gj >= 0) & (gj < NW);           \
            const float* src = inb ? ((PF) + gi * NW + gj) : (PF);              \
            cp_async16_z(&ps[BUF][r][c4 * 4], src, inb ? 16 : 0);               \
        }

    BWD_FILL(0, phib)
    cp_commit();

    int buf = 0;
    for (int ff = 0; ff < NFC; ++ff) {
        cp_wait0();
        __syncthreads();

        if (ff + 1 < NFC) {
            const float* pf = phib + (size_t)(ff + 1) * NH * NW;
            int ob = buf ^ 1;
            BWD_FILL(ob, pf)
            cp_commit();
        }

        {
            float wA[28];
            #pragma unroll
            for (int k = 0; k < 28; ++k) wA[k] = ws[ff * 49 + k];
            #pragma unroll
            for (int t0 = 0; t0 < 11; ++t0)
                stencil_rowA(&ps[buf][li + t0][lj + 2], t0, wA, acc);
        }
        {
            float wB[21];
            #pragma unroll
            for (int k = 0; k < 21; ++k) wB[k] = ws[ff * 49 + 28 + k];
            #pragma unroll
            for (int t0 = 4; t0 < 14; ++t0)
                stencil_rowB(&ps[buf][li + t0][lj + 2], t0, wB, acc);
        }
        buf ^= 1;
    }
    #undef BWD_FILL

    float* gout = d_g + (size_t)fc * NB * GP * GP + (size_t)b * GP * GP;
    #pragma unroll
    for (int i = 0; i < 8; ++i) {
        int m = m0 + li + i;
        int n = n0 + lj;
        if (m < GP) {
            if (n + 1 < GP) {
                *reinterpret_cast<float2*>(gout + m * GP + n) =
                    make_float2(acc[i][0], acc[i][1]);
            } else if (n < GP) {
                gout[m * GP + n] = acc[i][0];
            }
        }
    }
}

// ---------------- kernel D: fold + residual + prox ----------------
__global__ void finish_kernel(const float* __restrict__ input,
                              const float* __restrict__ noisy,
                              const float* __restrict__ a_cond,
                              float* __restrict__ out)
{
    int t = blockIdx.x * blockDim.x + threadIdx.x;
    if (t >= NB * NH * NW) return;
    int b   = t >> 16;
    int rem = t & 65535;
    int i = rem >> 8, j = rem & 255;

    const float* gb0 = d_g + (size_t)b * GP * GP;
    const float* gb1 = gb0 + (size_t)NB * GP * GP;

    int mi[2], nj[2];
    int nm = 1, nn = 1;
    mi[0] = i + 3;
    nj[0] = j + 3;
    if (i < 3)       mi[nm++] = 2 - i;
    if (i >= NH - 3) mi[nm++] = 2 * NH + 2 - i;
    if (j < 3)       nj[nn++] = 2 - j;
    if (j >= NW - 3) nj[nn++] = 2 * NW + 2 - j;

    float r = 0.f;
    for (int a = 0; a < nm; ++a)
        for (int c = 0; c < nn; ++c) {
            int off = mi[a] * GP + nj[c];
            r += gb0[off] + gb1[off];
        }

    float av = a_cond[b];
    float z = input[t] - r;
    float d = z - av;
    out[t] = 0.5f * (d + sqrtf(d * d + 4.0f * av * noisy[t]));
}

// ---------------- launch ----------------
extern "C" void kernel_launch(void* const* d_in, const int* in_sizes, int n_in,
                              void* d_out, int out_size)
{
    const float* input   = (const float*)d_in[0];
    const float* noisy   = (const float*)d_in[1];
    const float* a_cond  = (const float*)d_in[2];
    const float* cw      = (const float*)d_in[3];
    const float* sf      = (const float*)d_in[4];
    const float* rw      = (const float*)d_in[5];
    const float* centers = (const float*)d_in[6];
    const float* grid    = (const float*)d_in[7];
    float* out = (float*)d_out;

    prep_weights<<<1, 64>>>(cw, sf, grid);
    prep_table<<<NF, 128>>>(rw, centers, grid);
    fwd_kernel<<<dim3(8, 32, NB), 128>>>(input);   // 4 x-tiles x 2 f-chunks, 32 y-tiles
    bwd_kernel<<<dim3(10, 9, NB), 128>>>();
    finish_kernel<<<(NB * NH * NW + 255) / 256, 256>>>(input, noisy, a_cond, out);
}

// round 11
// speedup vs baseline: 1.3483x; 1.0521x over previous
#include <cuda_runtime.h>
#include <stdint.h>
#include <math.h>

#define NF 64
#define NFC 32
#define NC 51
#define LG 1001
#define NB 16
#define NH 256
#define NW 256
#define GP 262
#define PSIPLANE ((size_t)NB * NH * NW)   /* one tap plane: 1M px */

// ---------------- scratch ----------------
__device__ float  d_wn [NF * 49];
__device__ float  d_wnf[NF * 49];
__device__ float2 d_tab2[NF * 1000];
__device__ float  d_lut[3];
__device__ float  d_phi[(size_t)NB * NF * NH * NW];   // 256 MB
__device__ float  d_psi[49 * ((size_t)NB * NH * NW)]; // 205 MB
__device__ float  d_g  [NB * GP * GP];

// ---------------- helpers ----------------
__device__ __forceinline__ void cp_async16(void* sdst, const void* gsrc) {
    unsigned int sa = (unsigned int)__cvta_generic_to_shared(sdst);
    asm volatile("cp.async.cg.shared.global [%0], [%1], 16;\n" :: "r"(sa), "l"(gsrc));
}
__device__ __forceinline__ void cp_commit() { asm volatile("cp.async.commit_group;\n"); }
__device__ __forceinline__ void cp_wait0()  { asm volatile("cp.async.wait_group 0;\n"); }

__device__ __forceinline__ unsigned cvt_tf32(float v) {
    unsigned u;
    asm("cvt.rna.tf32.f32 %0, %1;" : "=r"(u) : "f"(v));
    return u;
}

__device__ __forceinline__ void mma_tf32(float& c0, float& c1, float& c2, float& c3,
                                         unsigned a0, unsigned a1, unsigned a2, unsigned a3,
                                         unsigned b0, unsigned b1) {
    asm volatile(
        "mma.sync.aligned.m16n8k8.row.col.f32.tf32.tf32.f32 "
        "{%0,%1,%2,%3}, {%4,%5,%6,%7}, {%8,%9}, {%0,%1,%2,%3};"
        : "+f"(c0), "+f"(c1), "+f"(c2), "+f"(c3)
        : "r"(a0), "r"(a1), "r"(a2), "r"(a3), "r"(b0), "r"(b1));
}

// ---------------- prep 1 ----------------
__global__ void prep_weights(const float* __restrict__ cw,
                             const float* __restrict__ sf,
                             const float* __restrict__ grid)
{
    int f = threadIdx.x;
    if (f < NF) {
        float s = 0.f;
        for (int k = 0; k < 49; ++k) s += cw[f * 49 + k];
        float mean = s / 49.0f;
        float ss = 0.f;
        for (int k = 0; k < 49; ++k) {
            float v = cw[f * 49 + k] - mean;
            ss += v * v;
        }
        float sc = sf[f] / sqrtf(ss);
        for (int k = 0; k < 49; ++k) {
            float v = (cw[f * 49 + k] - mean) * sc;
            d_wn[f * 49 + k] = v;
            int p = k / 7, q = k % 7;
            d_wnf[f * 49 + (6 - p) * 7 + (6 - q)] = v;
        }
    }
    if (threadIdx.x == 0) {
        d_lut[0] = grid[0];
        d_lut[1] = grid[LG - 1];
        d_lut[2] = 1.0f / (grid[1] - grid[0]);
    }
}

// ---------------- prep 2 ----------------
__global__ void prep_table(const float* __restrict__ rw,
                           const float* __restrict__ centers,
                           const float* __restrict__ grid)
{
    __shared__ float tl[LG];
    __shared__ float cs[NC];
    __shared__ float rs[NC];
    int f = blockIdx.x;
    int t = threadIdx.x;
    if (t < NC) { cs[t] = centers[t]; rs[t] = rw[f * NC + t]; }
    __syncthreads();
    for (int l = t; l < LG; l += blockDim.x) {
        float g = grid[l];
        float s = 0.f;
        #pragma unroll 1
        for (int c = 0; c < NC; ++c) {
            float dd = 0.25f * (g - cs[c]);
            s += rs[c] * expf(-0.5f * dd * dd);
        }
        tl[l] = s;
    }
    __syncthreads();
    for (int l = t; l < LG - 1; l += blockDim.x)
        d_tab2[f * 1000 + l] = make_float2(tl[l], tl[l + 1]);
}

// ---------------- kernel B: forward conv via mma.sync tf32 + LUT -> phi (R10) --------
__global__ void __launch_bounds__(128) fwd_kernel(const float* __restrict__ x)
{
    __shared__ float    xs[14][72];
    __shared__ unsigned ws[56 * 32];

    int b  = blockIdx.z;
    int i0 = blockIdx.y * 8;
    int xt = blockIdx.x & 3;
    int fc = blockIdx.x >> 2;
    int x0 = xt * 64;
    int f0 = fc * NFC;
    int tid = threadIdx.x;

    const float* xb_ptr = x + (size_t)b * NH * NW;

    for (int tpos = tid; tpos < 14 * 70; tpos += 128) {
        int r = tpos / 70, c = tpos - r * 70;
        int gi = i0 - 3 + r;
        int gj = x0 - 3 + c;
        gi = (gi < 0) ? (-1 - gi) : ((gi >= NH) ? (2 * NH - 1 - gi) : gi);
        gj = (gj < 0) ? (-1 - gj) : ((gj >= NW) ? (2 * NW - 1 - gj) : gj);
        xs[r][c] = xb_ptr[gi * NW + gj];
    }
    for (int tpos = tid; tpos < 56 * 32; tpos += 128) {
        int k = tpos >> 5, n = tpos & 31;
        ws[tpos] = (k < 49) ? cvt_tf32(d_wn[(f0 + n) * 49 + k]) : 0u;
    }
    __syncthreads();

    float g0 = d_lut[0], gmax = d_lut[1], invstep = d_lut[2];

    int lane = tid & 31, wrp = tid >> 5;
    int lam = lane & 3;
    int grp = lane >> 2;

    int offA[7][2];
    #pragma unroll
    for (int kk = 0; kk < 7; ++kk) {
        #pragma unroll
        for (int h = 0; h < 2; ++h) {
            int c = kk * 8 + lam + 4 * h;
            if (c > 48) c = 48;
            offA[kk][h] = (c / 7) * 72 + (c % 7);
        }
    }

    unsigned bfr[4][7][2];
    #pragma unroll
    for (int n = 0; n < 4; ++n)
        #pragma unroll
        for (int kk = 0; kk < 7; ++kk) {
            bfr[n][kk][0] = ws[(kk * 8 + lam) * 32 + n * 8 + grp];
            bfr[n][kk][1] = ws[(kk * 8 + lam + 4) * 32 + n * 8 + grp];
        }

    const float* xsf = &xs[0][0];

    #pragma unroll 1
    for (int mt = 0; mt < 8; ++mt) {
        int py = wrp * 2 + (mt >> 2);
        int xb = (mt & 3) * 16;
        int base = py * 72 + xb + grp;

        float acc[4][4];
        #pragma unroll
        for (int n = 0; n < 4; ++n)
            #pragma unroll
            for (int j = 0; j < 4; ++j) acc[n][j] = 0.f;

        #pragma unroll
        for (int kk = 0; kk < 7; ++kk) {
            unsigned a0 = __float_as_uint(xsf[base +     offA[kk][0]]);
            unsigned a1 = __float_as_uint(xsf[base + 8 + offA[kk][0]]);
            unsigned a2 = __float_as_uint(xsf[base +     offA[kk][1]]);
            unsigned a3 = __float_as_uint(xsf[base + 8 + offA[kk][1]]);
            #pragma unroll
            for (int n = 0; n < 4; ++n)
                mma_tf32(acc[n][0], acc[n][1], acc[n][2], acc[n][3],
                         a0, a1, a2, a3, bfr[n][kk][0], bfr[n][kk][1]);
        }

        int y = i0 + py;
        #pragma unroll
        for (int n = 0; n < 4; ++n) {
            #pragma unroll
            for (int j = 0; j < 4; ++j) {
                int f  = f0 + n * 8 + 2 * lam + (j & 1);
                int px = x0 + xb + grp + ((j >> 1) << 3);
                float v = fminf(fmaxf(acc[n][j], g0), gmax);
                float pos = (v - g0) * invstep;
                int idx = (int)floorf(pos);
                idx = idx < 0 ? 0 : (idx > 999 ? 999 : idx);
                float fr = pos - (float)idx;
                float2 tv = __ldg(d_tab2 + f * 1000 + idx);
                d_phi[(((size_t)(b * NF + f)) << 16) + (y << 8) + px] =
                    tv.x * (1.0f - fr) + tv.y * fr;
            }
        }
    }
}

// ---------------- kernel C1: psi GEMM  psi[uv][b][px] = sum_f wnf[f][uv] * phi[b][f][px]
// Block: 128 threads, 128 px x 56 taps, K=64. A staged transposed in smem.
#define SA_STRIDE 132
#define SB_STRIDE 57
__global__ void __launch_bounds__(128) psi_kernel()
{
    __shared__ float    sa[64 * SA_STRIDE];   // [f][px0..127]
    __shared__ unsigned sb[64 * SB_STRIDE];   // [f][uv], tf32, uv 49..55 zero

    int b   = blockIdx.y;
    int px0 = blockIdx.x * 128;
    int tid = threadIdx.x;

    // stage A: 64 f-rows x 512 B via cp.async
    const float* phib = d_phi + (((size_t)b * NF) << 16) + px0;
    for (int c = tid; c < 64 * 32; c += 128) {
        int f = c >> 5, c4 = c & 31;
        cp_async16(&sa[f * SA_STRIDE + c4 * 4], phib + ((size_t)f << 16) + c4 * 4);
    }
    cp_commit();

    // stage B
    for (int c = tid; c < 64 * 56; c += 128) {
        int f = c / 56, uv = c - f * 56;
        sb[f * SB_STRIDE + uv] = (uv < 49) ? cvt_tf32(d_wnf[f * 49 + uv]) : 0u;
    }
    cp_wait0();
    __syncthreads();

    int lane = tid & 31, wrp = tid >> 5;
    int lam = lane & 3;
    int grp = lane >> 2;

    float acc[2][7][4];
    #pragma unroll
    for (int mt = 0; mt < 2; ++mt)
        #pragma unroll
        for (int n = 0; n < 7; ++n)
            #pragma unroll
            for (int j = 0; j < 4; ++j) acc[mt][n][j] = 0.f;

    #pragma unroll
    for (int kk = 0; kk < 8; ++kk) {
        unsigned bf[7][2];
        #pragma unroll
        for (int n = 0; n < 7; ++n) {
            bf[n][0] = sb[(kk * 8 + lam)     * SB_STRIDE + n * 8 + grp];
            bf[n][1] = sb[(kk * 8 + lam + 4) * SB_STRIDE + n * 8 + grp];
        }
        #pragma unroll
        for (int mt = 0; mt < 2; ++mt) {
            int mrow = (wrp * 2 + mt) * 16;
            unsigned a0 = __float_as_uint(sa[(kk * 8 + lam)     * SA_STRIDE + mrow + grp]);
            unsigned a1 = __float_as_uint(sa[(kk * 8 + lam)     * SA_STRIDE + mrow + grp + 8]);
            unsigned a2 = __float_as_uint(sa[(kk * 8 + lam + 4) * SA_STRIDE + mrow + grp]);
            unsigned a3 = __float_as_uint(sa[(kk * 8 + lam + 4) * SA_STRIDE + mrow + grp + 8]);
            #pragma unroll
            for (int n = 0; n < 7; ++n)
                mma_tf32(acc[mt][n][0], acc[mt][n][1], acc[mt][n][2], acc[mt][n][3],
                         a0, a1, a2, a3, bf[n][0], bf[n][1]);
        }
    }

    // store psi
    size_t bpx = ((size_t)b << 16) + px0;
    #pragma unroll
    for (int mt = 0; mt < 2; ++mt) {
        #pragma unroll
        for (int n = 0; n < 7; ++n) {
            #pragma unroll
            for (int j = 0; j < 4; ++j) {
                int uv = n * 8 + 2 * lam + (j & 1);
                if (uv < 49) {
                    int pl = (wrp * 2 + mt) * 16 + grp + 8 * (j >> 1);
                    d_psi[(size_t)uv * PSIPLANE + bpx + pl] = acc[mt][n][j];
                }
            }
        }
    }
}

// ---------------- kernel C2: fold  g[m,n] = sum_uv psi[uv][m-6+u][n-6+v] -------------
__global__ void __launch_bounds__(256) fold_kernel()
{
    int t = blockIdx.x * 256 + threadIdx.x;
    if (t >= GP * GP) return;
    int b = blockIdx.y;
    int m = t / GP;
    int n = t - m * GP;

    float acc = 0.f;
    #pragma unroll
    for (int u = 0; u < 7; ++u) {
        int y = m - 6 + u;
        if ((unsigned)y < (unsigned)NH) {
            const float* base = d_psi + (size_t)(u * 7) * PSIPLANE
                              + ((size_t)b << 16) + (y << 8);
            #pragma unroll
            for (int v = 0; v < 7; ++v) {
                int xx = n - 6 + v;
                if ((unsigned)xx < (unsigned)NW)
                    acc += base[(size_t)v * PSIPLANE + xx];
            }
        }
    }
    d_g[(size_t)b * GP * GP + t] = acc;
}

// ---------------- kernel D: fold borders + residual + prox ----------------
__global__ void finish_kernel(const float* __restrict__ input,
                              const float* __restrict__ noisy,
                              const float* __restrict__ a_cond,
                              float* __restrict__ out)
{
    int t = blockIdx.x * blockDim.x + threadIdx.x;
    if (t >= NB * NH * NW) return;
    int b   = t >> 16;
    int rem = t & 65535;
    int i = rem >> 8, j = rem & 255;

    const float* gb = d_g + (size_t)b * GP * GP;

    int mi[2], nj[2];
    int nm = 1, nn = 1;
    mi[0] = i + 3;
    nj[0] = j + 3;
    if (i < 3)       mi[nm++] = 2 - i;
    if (i >= NH - 3) mi[nm++] = 2 * NH + 2 - i;
    if (j < 3)       nj[nn++] = 2 - j;
    if (j >= NW - 3) nj[nn++] = 2 * NW + 2 - j;

    float r = 0.f;
    for (int a = 0; a < nm; ++a)
        for (int c = 0; c < nn; ++c)
            r += gb[mi[a] * GP + nj[c]];

    float av = a_cond[b];
    float z = input[t] - r;
    float d = z - av;
    out[t] = 0.5f * (d + sqrtf(d * d + 4.0f * av * noisy[t]));
}

// ---------------- launch ----------------
extern "C" void kernel_launch(void* const* d_in, const int* in_sizes, int n_in,
                              void* d_out, int out_size)
{
    const float* input   = (const float*)d_in[0];
    const float* noisy   = (const float*)d_in[1];
    const float* a_cond  = (const float*)d_in[2];
    const float* cw      = (const float*)d_in[3];
    const float* sf      = (const float*)d_in[4];
    const float* rw      = (const float*)d_in[5];
    const float* centers = (const float*)d_in[6];
    const float* grid    = (const float*)d_in[7];
    float* out = (float*)d_out;

    prep_weights<<<1, 64>>>(cw, sf, grid);
    prep_table<<<NF, 128>>>(rw, centers, grid);
    fwd_kernel<<<dim3(8, 32, NB), 128>>>(input);
    psi_kernel<<<dim3(512, NB), 128>>>();
    fold_kernel<<<dim3((GP * GP + 255) / 256, NB), 256>>>();
    finish_kernel<<<(NB * NH * NW + 255) / 256, 256>>>(input, noisy, a_cond, out);
}

// round 12
// speedup vs baseline: 1.4921x; 1.1067x over previous
#include <cuda_runtime.h>
#include <stdint.h>
#include <math.h>

#define NF 64
#define NFC 32
#define NC 51
#define LG 1001
#define NB 16
#define NH 256
#define NW 256
#define GP 262
#define PSIPLANE ((size_t)NB * NH * NW)

// ---------------- scratch ----------------
__device__ float  d_wn [NF * 49];
__device__ float  d_wnf[NF * 49];
__device__ float2 d_tab2[NF * 1000];
__device__ float  d_lut[3];
__device__ float  d_phi[(size_t)NB * NF * NH * NW];   // 256 MB
__device__ float  d_psi[49 * ((size_t)NB * NH * NW)]; // 205 MB
__device__ float  d_g  [NB * GP * GP];

// ---------------- helpers ----------------
__device__ __forceinline__ void cp_async16(void* sdst, const void* gsrc) {
    unsigned int sa = (unsigned int)__cvta_generic_to_shared(sdst);
    asm volatile("cp.async.cg.shared.global [%0], [%1], 16;\n" :: "r"(sa), "l"(gsrc));
}
__device__ __forceinline__ void cp_commit() { asm volatile("cp.async.commit_group;\n"); }
__device__ __forceinline__ void cp_wait0()  { asm volatile("cp.async.wait_group 0;\n"); }
__device__ __forceinline__ void cp_wait1()  { asm volatile("cp.async.wait_group 1;\n"); }

__device__ __forceinline__ unsigned cvt_tf32(float v) {
    unsigned u;
    asm("cvt.rna.tf32.f32 %0, %1;" : "=r"(u) : "f"(v));
    return u;
}

__device__ __forceinline__ void mma_tf32(float& c0, float& c1, float& c2, float& c3,
                                         unsigned a0, unsigned a1, unsigned a2, unsigned a3,
                                         unsigned b0, unsigned b1) {
    asm volatile(
        "mma.sync.aligned.m16n8k8.row.col.f32.tf32.tf32.f32 "
        "{%0,%1,%2,%3}, {%4,%5,%6,%7}, {%8,%9}, {%0,%1,%2,%3};"
        : "+f"(c0), "+f"(c1), "+f"(c2), "+f"(c3)
        : "r"(a0), "r"(a1), "r"(a2), "r"(a3), "r"(b0), "r"(b1));
}

// ---------------- prep 1 ----------------
__global__ void prep_weights(const float* __restrict__ cw,
                             const float* __restrict__ sf,
                             const float* __restrict__ grid)
{
    int f = threadIdx.x;
    if (f < NF) {
        float s = 0.f;
        for (int k = 0; k < 49; ++k) s += cw[f * 49 + k];
        float mean = s / 49.0f;
        float ss = 0.f;
        for (int k = 0; k < 49; ++k) {
            float v = cw[f * 49 + k] - mean;
            ss += v * v;
        }
        float sc = sf[f] / sqrtf(ss);
        for (int k = 0; k < 49; ++k) {
            float v = (cw[f * 49 + k] - mean) * sc;
            d_wn[f * 49 + k] = v;
            int p = k / 7, q = k % 7;
            d_wnf[f * 49 + (6 - p) * 7 + (6 - q)] = v;
        }
    }
    if (threadIdx.x == 0) {
        d_lut[0] = grid[0];
        d_lut[1] = grid[LG - 1];
        d_lut[2] = 1.0f / (grid[1] - grid[0]);
    }
}

// ---------------- prep 2 ----------------
__global__ void prep_table(const float* __restrict__ rw,
                           const float* __restrict__ centers,
                           const float* __restrict__ grid)
{
    __shared__ float tl[LG];
    __shared__ float cs[NC];
    __shared__ float rs[NC];
    int f = blockIdx.x;
    int t = threadIdx.x;
    if (t < NC) { cs[t] = centers[t]; rs[t] = rw[f * NC + t]; }
    __syncthreads();
    for (int l = t; l < LG; l += blockDim.x) {
        float g = grid[l];
        float s = 0.f;
        #pragma unroll 1
        for (int c = 0; c < NC; ++c) {
            float dd = 0.25f * (g - cs[c]);
            s += rs[c] * expf(-0.5f * dd * dd);
        }
        tl[l] = s;
    }
    __syncthreads();
    for (int l = t; l < LG - 1; l += blockDim.x)
        d_tab2[f * 1000 + l] = make_float2(tl[l], tl[l + 1]);
}

// ---------------- kernel B: forward conv via mma.sync tf32 + LUT -> phi --------
__global__ void __launch_bounds__(128) fwd_kernel(const float* __restrict__ x)
{
    __shared__ float    xs[14][72];
    __shared__ unsigned ws[56 * 32];

    int b  = blockIdx.z;
    int i0 = blockIdx.y * 8;
    int xt = blockIdx.x & 3;
    int fc = blockIdx.x >> 2;
    int x0 = xt * 64;
    int f0 = fc * NFC;
    int tid = threadIdx.x;

    const float* xb_ptr = x + (size_t)b * NH * NW;

    for (int tpos = tid; tpos < 14 * 70; tpos += 128) {
        int r = tpos / 70, c = tpos - r * 70;
        int gi = i0 - 3 + r;
        int gj = x0 - 3 + c;
        gi = (gi < 0) ? (-1 - gi) : ((gi >= NH) ? (2 * NH - 1 - gi) : gi);
        gj = (gj < 0) ? (-1 - gj) : ((gj >= NW) ? (2 * NW - 1 - gj) : gj);
        xs[r][c] = xb_ptr[gi * NW + gj];
    }
    for (int tpos = tid; tpos < 56 * 32; tpos += 128) {
        int k = tpos >> 5, n = tpos & 31;
        ws[tpos] = (k < 49) ? cvt_tf32(d_wn[(f0 + n) * 49 + k]) : 0u;
    }
    __syncthreads();

    float g0 = d_lut[0], gmax = d_lut[1], invstep = d_lut[2];

    int lane = tid & 31, wrp = tid >> 5;
    int lam = lane & 3;
    int grp = lane >> 2;

    int offA[7][2];
    #pragma unroll
    for (int kk = 0; kk < 7; ++kk) {
        #pragma unroll
        for (int h = 0; h < 2; ++h) {
            int c = kk * 8 + lam + 4 * h;
            if (c > 48) c = 48;
            offA[kk][h] = (c / 7) * 72 + (c % 7);
        }
    }

    unsigned bfr[4][7][2];
    #pragma unroll
    for (int n = 0; n < 4; ++n)
        #pragma unroll
        for (int kk = 0; kk < 7; ++kk) {
            bfr[n][kk][0] = ws[(kk * 8 + lam) * 32 + n * 8 + grp];
            bfr[n][kk][1] = ws[(kk * 8 + lam + 4) * 32 + n * 8 + grp];
        }

    const float* xsf = &xs[0][0];

    #pragma unroll 1
    for (int mt = 0; mt < 8; ++mt) {
        int py = wrp * 2 + (mt >> 2);
        int xb = (mt & 3) * 16;
        int base = py * 72 + xb + grp;

        float acc[4][4];
        #pragma unroll
        for (int n = 0; n < 4; ++n)
            #pragma unroll
            for (int j = 0; j < 4; ++j) acc[n][j] = 0.f;

        #pragma unroll
        for (int kk = 0; kk < 7; ++kk) {
            unsigned a0 = __float_as_uint(xsf[base +     offA[kk][0]]);
            unsigned a1 = __float_as_uint(xsf[base + 8 + offA[kk][0]]);
            unsigned a2 = __float_as_uint(xsf[base +     offA[kk][1]]);
            unsigned a3 = __float_as_uint(xsf[base + 8 + offA[kk][1]]);
            #pragma unroll
            for (int n = 0; n < 4; ++n)
                mma_tf32(acc[n][0], acc[n][1], acc[n][2], acc[n][3],
                         a0, a1, a2, a3, bfr[n][kk][0], bfr[n][kk][1]);
        }

        int y = i0 + py;
        #pragma unroll
        for (int n = 0; n < 4; ++n) {
            #pragma unroll
            for (int j = 0; j < 4; ++j) {
                int f  = f0 + n * 8 + 2 * lam + (j & 1);
                int px = x0 + xb + grp + ((j >> 1) << 3);
                float v = fminf(fmaxf(acc[n][j], g0), gmax);
                float pos = (v - g0) * invstep;
                int idx = (int)floorf(pos);
                idx = idx < 0 ? 0 : (idx > 999 ? 999 : idx);
                float fr = pos - (float)idx;
                float2 tv = __ldg(d_tab2 + f * 1000 + idx);
                d_phi[(((size_t)(b * NF + f)) << 16) + (y << 8) + px] =
                    tv.x * (1.0f - fr) + tv.y * fr;
            }
        }
    }
}

// ---------------- kernel C1: psi GEMM, software-pipelined ----------------
// Each block: 4 tiles of 128 px; K=64 staged as 2 chunks of 32 filters,
// double-buffered via cp.async. B (tf32 weights) loaded once per block.
#define KC 32
#define SA_STRIDE 132
#define SB_STRIDE 57
#define NSTEP 8              /* 4 tiles x 2 k-chunks */
__global__ void __launch_bounds__(128) psi_kernel()
{
    __shared__ float    sa[2][KC * SA_STRIDE];   // 2 x 16.5 KB
    __shared__ unsigned sb[64 * SB_STRIDE];      // 14.25 KB

    int b     = blockIdx.y;
    int tile0 = blockIdx.x * 4;
    int tid   = threadIdx.x;

    // B once per block
    for (int c = tid; c < 64 * 56; c += 128) {
        int f = c / 56, uv = c - f * 56;
        sb[f * SB_STRIDE + uv] = (uv < 49) ? cvt_tf32(d_wnf[f * 49 + uv]) : 0u;
    }

    const float* phib = d_phi + (((size_t)b * NF) << 16);

    // stage step s (tile = s/2, kchunk = s%2) into buffer s&1
    #define PSI_STAGE(S)                                                        \
        {                                                                       \
            int t_ = (S) >> 1, kc_ = (S) & 1;                                   \
            const float* src = phib + (((size_t)(kc_ * KC)) << 16)              \
                             + (size_t)(tile0 + t_) * 128;                      \
            for (int c = tid; c < KC * 32; c += 128) {                          \
                int f_ = c >> 5, c4 = c & 31;                                   \
                cp_async16(&sa[(S) & 1][f_ * SA_STRIDE + c4 * 4],               \
                           src + (((size_t)f_) << 16) + c4 * 4);                \
            }                                                                   \
            cp_commit();                                                        \
        }

    PSI_STAGE(0)

    int lane = tid & 31, wrp = tid >> 5;
    int lam = lane & 3;
    int grp = lane >> 2;

    float acc[2][7][4];

    #pragma unroll 1
    for (int s = 0; s < NSTEP; ++s) {
        int kc = s & 1;

        if (s + 1 < NSTEP) { PSI_STAGE(s + 1) cp_wait1(); }
        else               { cp_wait0(); }
        __syncthreads();

        if (kc == 0) {
            #pragma unroll
            for (int mt = 0; mt < 2; ++mt)
                #pragma unroll
                for (int n = 0; n < 7; ++n)
                    #pragma unroll
                    for (int j = 0; j < 4; ++j) acc[mt][n][j] = 0.f;
        }

        const float* sab = sa[s & 1];
        #pragma unroll
        for (int kk = 0; kk < 4; ++kk) {
            int fg = kc * KC + kk * 8;          // global filter base for B
            unsigned bf[7][2];
            #pragma unroll
            for (int n = 0; n < 7; ++n) {
                bf[n][0] = sb[(fg + lam)     * SB_STRIDE + n * 8 + grp];
                bf[n][1] = sb[(fg + lam + 4) * SB_STRIDE + n * 8 + grp];
            }
            #pragma unroll
            for (int mt = 0; mt < 2; ++mt) {
                int mrow = (wrp * 2 + mt) * 16;
                unsigned a0 = __float_as_uint(sab[(kk * 8 + lam)     * SA_STRIDE + mrow + grp]);
                unsigned a1 = __float_as_uint(sab[(kk * 8 + lam)     * SA_STRIDE + mrow + grp + 8]);
                unsigned a2 = __float_as_uint(sab[(kk * 8 + lam + 4) * SA_STRIDE + mrow + grp]);
                unsigned a3 = __float_as_uint(sab[(kk * 8 + lam + 4) * SA_STRIDE + mrow + grp + 8]);
                #pragma unroll
                for (int n = 0; n < 7; ++n)
                    mma_tf32(acc[mt][n][0], acc[mt][n][1], acc[mt][n][2], acc[mt][n][3],
                             a0, a1, a2, a3, bf[n][0], bf[n][1]);
            }
        }

        if (kc == 1) {
            size_t bpx = ((size_t)b << 16) + (size_t)(tile0 + (s >> 1)) * 128;
            #pragma unroll
            for (int mt = 0; mt < 2; ++mt) {
                #pragma unroll
                for (int n = 0; n < 7; ++n) {
                    #pragma unroll
                    for (int j = 0; j < 4; ++j) {
                        int uv = n * 8 + 2 * lam + (j & 1);
                        if (uv < 49) {
                            int pl = (wrp * 2 + mt) * 16 + grp + 8 * (j >> 1);
                            d_psi[(size_t)uv * PSIPLANE + bpx + pl] = acc[mt][n][j];
                        }
                    }
                }
            }
        }
        __syncthreads();
    }
    #undef PSI_STAGE
}

// ---------------- kernel C2: fold ----------------
__global__ void __launch_bounds__(256) fold_kernel()
{
    int t = blockIdx.x * 256 + threadIdx.x;
    if (t >= GP * GP) return;
    int b = blockIdx.y;
    int m = t / GP;
    int n = t - m * GP;

    float acc = 0.f;
    #pragma unroll
    for (int u = 0; u < 7; ++u) {
        int y = m - 6 + u;
        if ((unsigned)y < (unsigned)NH) {
            const float* base = d_psi + (size_t)(u * 7) * PSIPLANE
                              + ((size_t)b << 16) + (y << 8);
            #pragma unroll
            for (int v = 0; v < 7; ++v) {
                int xx = n - 6 + v;
                if ((unsigned)xx < (unsigned)NW)
                    acc += base[(size_t)v * PSIPLANE + xx];
            }
        }
    }
    d_g[(size_t)b * GP * GP + t] = acc;
}

// ---------------- kernel D: fold borders + residual + prox ----------------
__global__ void finish_kernel(const float* __restrict__ input,
                              const float* __restrict__ noisy,
                              const float* __restrict__ a_cond,
                              float* __restrict__ out)
{
    int t = blockIdx.x * blockDim.x + threadIdx.x;
    if (t >= NB * NH * NW) return;
    int b   = t >> 16;
    int rem = t & 65535;
    int i = rem >> 8, j = rem & 255;

    const float* gb = d_g + (size_t)b * GP * GP;

    int mi[2], nj[2];
    int nm = 1, nn = 1;
    mi[0] = i + 3;
    nj[0] = j + 3;
    if (i < 3)       mi[nm++] = 2 - i;
    if (i >= NH - 3) mi[nm++] = 2 * NH + 2 - i;
    if (j < 3)       nj[nn++] = 2 - j;
    if (j >= NW - 3) nj[nn++] = 2 * NW + 2 - j;

    float r = 0.f;
    for (int a = 0; a < nm; ++a)
        for (int c = 0; c < nn; ++c)
            r += gb[mi[a] * GP + nj[c]];

    float av = a_cond[b];
    float z = input[t] - r;
    float d = z - av;
    out[t] = 0.5f * (d + sqrtf(d * d + 4.0f * av * noisy[t]));
}

// ---------------- launch ----------------
extern "C" void kernel_launch(void* const* d_in, const int* in_sizes, int n_in,
                              void* d_out, int out_size)
{
    const float* input   = (const float*)d_in[0];
    const float* noisy   = (const float*)d_in[1];
    const float* a_cond  = (const float*)d_in[2];
    const float* cw      = (const float*)d_in[3];
    const float* sf      = (const float*)d_in[4];
    const float* rw      = (const float*)d_in[5];
    const float* centers = (const float*)d_in[6];
    const float* grid    = (const float*)d_in[7];
    float* out = (float*)d_out;

    prep_weights<<<1, 64>>>(cw, sf, grid);
    prep_table<<<NF, 128>>>(rw, centers, grid);
    fwd_kernel<<<dim3(8, 32, NB), 128>>>(input);
    psi_kernel<<<dim3(128, NB), 128>>>();
    fold_kernel<<<dim3((GP * GP + 255) / 256, NB), 256>>>();
    finish_kernel<<<(NB * NH * NW + 255) / 256, 256>>>(input, noisy, a_cond, out);
}